// round 1
// baseline (speedup 1.0000x reference)
#include <cuda_runtime.h>
#include <math.h>

#define BATCH 8
#define SEQ   256
#define F0    512
#define F1    256
#define F2    128
#define KMAX  30

// ---- scratch (no allocations allowed; __device__ globals) ----
__device__ float g_h[BATCH*SEQ*F1];
__device__ float g_z[BATCH*SEQ*F2];
__device__ float g_corr[BATCH*SEQ*SEQ];
__device__ float g_D[BATCH*SEQ*SEQ];
__device__ float g_tmp[BATCH*SEQ*SEQ];
__device__ float g_P[BATCH*SEQ*SEQ];      // P[n+1][i+1] stored at [n][i]
__device__ float g_Ds[BATCH*SEQ*SEQ];
__device__ float g_numer[BATCH*SEQ];

// ============================================================
// GEMM: C[M,N] = (A[M,K] @ B[K,N]) + bias, optional relu.
// 64x64 tile, BK=16, 256 threads, 4x4 per thread. fp32 FMA.
// ============================================================
template<int RELU>
__global__ __launch_bounds__(256) void gemm_kernel(
    const float* __restrict__ A, const float* __restrict__ B,
    const float* __restrict__ bias, float* __restrict__ C,
    int M, int N, int K)
{
    __shared__ float As[16][64];   // As[k][m]
    __shared__ float Bs[16][64];   // Bs[k][n]
    const int m0 = blockIdx.y * 64, n0 = blockIdx.x * 64;
    const int tid = threadIdx.x;
    const int ty = tid >> 4, tx = tid & 15;
    const int arow = tid >> 2, akq = tid & 3;     // A loader: 64 rows x 4 float4
    const int bkr  = tid >> 4, bnq = tid & 15;    // B loader: 16 rows x 16 float4

    float acc[4][4] = {};

    for (int k0 = 0; k0 < K; k0 += 16) {
        float4 va = *(const float4*)(A + (size_t)(m0 + arow) * K + k0 + akq * 4);
        As[akq*4+0][arow] = va.x; As[akq*4+1][arow] = va.y;
        As[akq*4+2][arow] = va.z; As[akq*4+3][arow] = va.w;
        float4 vb = *(const float4*)(B + (size_t)(k0 + bkr) * N + n0 + bnq * 4);
        *(float4*)&Bs[bkr][bnq*4] = vb;
        __syncthreads();
        #pragma unroll
        for (int k = 0; k < 16; k++) {
            float4 a4 = *(const float4*)&As[k][ty*4];
            float4 b4 = *(const float4*)&Bs[k][tx*4];
            float av[4] = {a4.x, a4.y, a4.z, a4.w};
            float bv[4] = {b4.x, b4.y, b4.z, b4.w};
            #pragma unroll
            for (int r = 0; r < 4; r++)
                #pragma unroll
                for (int c = 0; c < 4; c++)
                    acc[r][c] += av[r] * bv[c];
        }
        __syncthreads();
    }

    #pragma unroll
    for (int r = 0; r < 4; r++) {
        int m = m0 + ty*4 + r;
        #pragma unroll
        for (int c = 0; c < 4; c++) {
            int n = n0 + tx*4 + c;
            float v = acc[r][c] + bias[n];
            if (RELU) v = fmaxf(v, 0.0f);
            C[(size_t)m * N + n] = v;
        }
    }
}

// ============================================================
// corr[b] = z_b @ z_b^T   (NT gemm, M=N=256, K=128)
// ============================================================
__global__ __launch_bounds__(256) void syrk_kernel()
{
    __shared__ float As[16][64];
    __shared__ float Bs[16][64];
    const float* Z = g_z + (size_t)blockIdx.z * SEQ * F2;
    float* C = g_corr + (size_t)blockIdx.z * SEQ * SEQ;
    const int m0 = blockIdx.y * 64, n0 = blockIdx.x * 64;
    const int tid = threadIdx.x;
    const int ty = tid >> 4, tx = tid & 15;
    const int row = tid >> 2, kq = tid & 3;

    float acc[4][4] = {};

    for (int k0 = 0; k0 < F2; k0 += 16) {
        float4 va = *(const float4*)(Z + (size_t)(m0 + row) * F2 + k0 + kq * 4);
        As[kq*4+0][row] = va.x; As[kq*4+1][row] = va.y;
        As[kq*4+2][row] = va.z; As[kq*4+3][row] = va.w;
        float4 vb = *(const float4*)(Z + (size_t)(n0 + row) * F2 + k0 + kq * 4);
        Bs[kq*4+0][row] = vb.x; Bs[kq*4+1][row] = vb.y;
        Bs[kq*4+2][row] = vb.z; Bs[kq*4+3][row] = vb.w;
        __syncthreads();
        #pragma unroll
        for (int k = 0; k < 16; k++) {
            float4 a4 = *(const float4*)&As[k][ty*4];
            float4 b4 = *(const float4*)&Bs[k][tx*4];
            float av[4] = {a4.x, a4.y, a4.z, a4.w};
            float bv[4] = {b4.x, b4.y, b4.z, b4.w};
            #pragma unroll
            for (int r = 0; r < 4; r++)
                #pragma unroll
                for (int c = 0; c < 4; c++)
                    acc[r][c] += av[r] * bv[c];
        }
        __syncthreads();
    }

    #pragma unroll
    for (int r = 0; r < 4; r++) {
        int m = m0 + ty*4 + r;
        #pragma unroll
        for (int c = 0; c < 4; c++) {
            int n = n0 + tx*4 + c;
            C[(size_t)m * SEQ + n] = acc[r][c];
        }
    }
}

// ============================================================
// D = (1 - corr / sqrt(max(d_n*d_i, 1e-8))) / 2
// ============================================================
__global__ __launch_bounds__(256) void computeD_kernel()
{
    const int b = blockIdx.y, n = blockIdx.x, i = threadIdx.x;
    const float* cb = g_corr + (size_t)b * SEQ * SEQ;
    float dn = cb[n*SEQ + n];
    float di = cb[i*SEQ + i];
    float denom = sqrtf(fmaxf(dn * di, 1e-8f));
    float c = cb[n*SEQ + i];
    g_D[(size_t)b*SEQ*SEQ + n*SEQ + i] = (1.0f - c / denom) * 0.5f;
}

// cumsum over n (axis=1), sequential left-fold to match jnp.cumsum
__global__ __launch_bounds__(256) void scan_rows_kernel()
{
    const int b = blockIdx.x, i = threadIdx.x;
    const float* Db = g_D + (size_t)b * SEQ * SEQ;
    float* Tb = g_tmp + (size_t)b * SEQ * SEQ;
    float run = 0.0f;
    for (int n = 0; n < SEQ; n++) { run += Db[n*SEQ + i]; Tb[n*SEQ + i] = run; }
}

// cumsum over i (axis=2), sequential left-fold
__global__ __launch_bounds__(256) void scan_cols_kernel()
{
    const int b = blockIdx.x, n = threadIdx.x;
    const float* Tb = g_tmp + (size_t)b * SEQ * SEQ;
    float* Pb = g_P + (size_t)b * SEQ * SEQ;
    float run = 0.0f;
    for (int i = 0; i < SEQ; i++) { run += Tb[n*SEQ + i]; Pb[n*SEQ + i] = run; }
}

// Ds[n][i] = P[hi+1,hi+1] - P[lo,hi+1] - P[hi+1,lo] + P[lo,lo]; subdiag -> D
__global__ __launch_bounds__(256) void buildDs_kernel()
{
    const int b = blockIdx.y, n = blockIdx.x, i = threadIdx.x;
    const float* Pb = g_P + (size_t)b * SEQ * SEQ;
    const float* Db = g_D + (size_t)b * SEQ * SEQ;
    int lo = min(n, i), hi = max(n, i);
    float a  = Pb[hi*SEQ + hi];                               // P[hi+1][hi+1]
    float bb = (lo == 0) ? 0.0f : Pb[(lo-1)*SEQ + hi];        // P[lo][hi+1]
    float cc = (lo == 0) ? 0.0f : Pb[hi*SEQ + (lo-1)];        // P[hi+1][lo]
    float dd = (lo == 0) ? 0.0f : Pb[(lo-1)*SEQ + (lo-1)];    // P[lo][lo]
    float v = ((a - bb) - cc) + dd;
    if (n - i == 1) v = Db[n*SEQ + i];
    g_Ds[(size_t)b*SEQ*SEQ + n*SEQ + i] = v;
}

// ============================================================
// Phase C: 30-step DP. One block per batch (syncthreads between
// steps), warp-per-row, 8 strided elems per lane, butterfly
// reductions. min(T) doubles as the softmax shift.
// ============================================================
__global__ __launch_bounds__(1024) void phaseC_kernel()
{
    __shared__ float accW[32][SEQ];     // per-warp accumulator, 32 KB
    __shared__ float Cprev[SEQ + 1];
    __shared__ float Cnext[SEQ];
    const int b = blockIdx.x;
    const int tid = threadIdx.x, w = tid >> 5, l = tid & 31;
    const float* Ds = g_Ds + (size_t)b * SEQ * SEQ;

    for (int i = tid; i < 32*SEQ; i += 1024) (&accW[0][0])[i] = 0.0f;
    if (tid < SEQ) Cprev[tid] = Ds[(size_t)tid * SEQ + (SEQ - 1)];
    if (tid == SEQ) Cprev[SEQ] = 0.0f;
    __syncthreads();

    for (int kk = 1; kk < KMAX; kk++) {
        const int limit = SEQ - kk;
        for (int n = w; n < limit; n += 32) {
            const float* row = Ds + (size_t)n * SEQ;
            float t[8];
            float mn = 3.0e38f;
            #pragma unroll
            for (int j = 0; j < 8; j++) {
                int i = l + 32*j;
                bool valid = (i >= n) & (i < limit);
                float v = valid ? (row[i] + Cprev[i + 1]) : 3.0e38f;
                t[j] = v;
                mn = fminf(mn, v);
            }
            #pragma unroll
            for (int off = 16; off > 0; off >>= 1)
                mn = fminf(mn, __shfl_xor_sync(0xffffffffu, mn, off));

            float e[8];
            float s = 0.0f;
            #pragma unroll
            for (int j = 0; j < 8; j++) {
                int i = l + 32*j;
                bool valid = (i >= n) & (i < limit);
                float ev = valid ? expf(mn - t[j]) : 0.0f;
                e[j] = ev;
                s += ev;
            }
            #pragma unroll
            for (int off = 16; off > 0; off >>= 1)
                s += __shfl_xor_sync(0xffffffffu, s, off);

            float inv = 1.0f / s;
            #pragma unroll
            for (int j = 0; j < 8; j++) {
                int i = l + 32*j;
                if ((i >= n) & (i < limit))
                    accW[w][i] += e[j] * inv;     // bank = lane, conflict-free
            }
            if (l == 0) Cnext[n] = mn;
        }
        __syncthreads();
        if (tid < SEQ) Cprev[tid] = (tid < limit) ? Cnext[tid] : 0.0f;
        __syncthreads();
    }

    for (int i = tid; i < SEQ; i += 1024) {
        float sum = 0.0f;
        #pragma unroll
        for (int w2 = 0; w2 < 32; w2++) sum += accW[w2][i];
        g_numer[b*SEQ + i] = sum;
    }
}

// out[b][i] = (numer + k0-term) / exact mask count
__global__ __launch_bounds__(256) void finalize_kernel(float* __restrict__ out)
{
    const int idx = blockIdx.x * SEQ + threadIdx.x;
    const int i = idx & (SEQ - 1);
    int m = min(KMAX - 1, SEQ - 1 - i);
    float cnt = (float)((i + 1) * m + ((i == SEQ - 1) ? SEQ : 0));
    float num = g_numer[idx] + ((i == SEQ - 1) ? (float)SEQ : 0.0f);
    out[idx] = num / cnt;
}

// ============================================================
extern "C" void kernel_launch(void* const* d_in, const int* in_sizes, int n_in,
                              void* d_out, int out_size)
{
    const float* x  = (const float*)d_in[0];
    const float* W0 = (const float*)d_in[1];
    const float* b0 = (const float*)d_in[2];
    const float* W1 = (const float*)d_in[3];
    const float* b1 = (const float*)d_in[4];
    float* out = (float*)d_out;

    static float* p_h = nullptr;
    static float* p_z = nullptr;
    if (!p_h) {
        cudaGetSymbolAddress((void**)&p_h, g_h);
        cudaGetSymbolAddress((void**)&p_z, g_z);
    }

    gemm_kernel<1><<<dim3(F1/64, (BATCH*SEQ)/64), 256>>>(x,   W0, b0, p_h, BATCH*SEQ, F1, F0);
    gemm_kernel<0><<<dim3(F2/64, (BATCH*SEQ)/64), 256>>>(p_h, W1, b1, p_z, BATCH*SEQ, F2, F1);
    syrk_kernel   <<<dim3(SEQ/64, SEQ/64, BATCH), 256>>>();
    computeD_kernel<<<dim3(SEQ, BATCH), SEQ>>>();
    scan_rows_kernel<<<BATCH, SEQ>>>();
    scan_cols_kernel<<<BATCH, SEQ>>>();
    buildDs_kernel<<<dim3(SEQ, BATCH), SEQ>>>();
    phaseC_kernel <<<BATCH, 1024>>>();
    finalize_kernel<<<BATCH, SEQ>>>(out);
}

// round 2
// speedup vs baseline: 1.5168x; 1.5168x over previous
#include <cuda_runtime.h>
#include <math.h>

#define BATCH 8
#define SEQ   256
#define F0    512
#define F1    256
#define F2    128
#define KMAX  30
#define PCB   16      // phaseC blocks per batch (8*16 = 128 blocks, one wave)
#define PCT   512     // threads per phaseC block (16 warps)

// ---- scratch (__device__ globals; no allocations allowed) ----
__device__ float g_h[BATCH*SEQ*F1];
__device__ float g_z[BATCH*SEQ*F2];
__device__ float g_corr[BATCH*SEQ*SEQ];
__device__ float g_D[BATCH*SEQ*SEQ];
__device__ float g_tmp[BATCH*SEQ*SEQ];
__device__ float g_P[BATCH*SEQ*SEQ];      // P[n+1][i+1] stored at [n][i]
__device__ float g_Ds[BATCH*SEQ*SEQ];
__device__ float g_Cbuf[2][BATCH][SEQ];   // DP C-vector, double buffered
__device__ int   g_ctr[BATCH][KMAX];      // per-step arrival counters
__device__ float g_part[BATCH][PCB][SEQ]; // per-block partial numerators

// ============================================================
// GEMM: C[M,N] = (A[M,K] @ B[K,N]) + bias, optional relu.
// 64x64 tile, BK=16, 256 threads, 4x4 per thread. fp32 FMA.
// ============================================================
template<int RELU>
__global__ __launch_bounds__(256) void gemm_kernel(
    const float* __restrict__ A, const float* __restrict__ B,
    const float* __restrict__ bias, float* __restrict__ C,
    int M, int N, int K)
{
    __shared__ float As[16][64];   // As[k][m]
    __shared__ float Bs[16][64];   // Bs[k][n]
    const int m0 = blockIdx.y * 64, n0 = blockIdx.x * 64;
    const int tid = threadIdx.x;
    const int ty = tid >> 4, tx = tid & 15;
    const int arow = tid >> 2, akq = tid & 3;
    const int bkr  = tid >> 4, bnq = tid & 15;

    float acc[4][4] = {};

    for (int k0 = 0; k0 < K; k0 += 16) {
        float4 va = *(const float4*)(A + (size_t)(m0 + arow) * K + k0 + akq * 4);
        As[akq*4+0][arow] = va.x; As[akq*4+1][arow] = va.y;
        As[akq*4+2][arow] = va.z; As[akq*4+3][arow] = va.w;
        float4 vb = *(const float4*)(B + (size_t)(k0 + bkr) * N + n0 + bnq * 4);
        *(float4*)&Bs[bkr][bnq*4] = vb;
        __syncthreads();
        #pragma unroll
        for (int k = 0; k < 16; k++) {
            float4 a4 = *(const float4*)&As[k][ty*4];
            float4 b4 = *(const float4*)&Bs[k][tx*4];
            float av[4] = {a4.x, a4.y, a4.z, a4.w};
            float bv[4] = {b4.x, b4.y, b4.z, b4.w};
            #pragma unroll
            for (int r = 0; r < 4; r++)
                #pragma unroll
                for (int c = 0; c < 4; c++)
                    acc[r][c] += av[r] * bv[c];
        }
        __syncthreads();
    }

    #pragma unroll
    for (int r = 0; r < 4; r++) {
        int m = m0 + ty*4 + r;
        #pragma unroll
        for (int c = 0; c < 4; c++) {
            int n = n0 + tx*4 + c;
            float v = acc[r][c] + bias[n];
            if (RELU) v = fmaxf(v, 0.0f);
            C[(size_t)m * N + n] = v;
        }
    }
}

// ============================================================
// corr[b] = z_b @ z_b^T   (NT gemm, M=N=256, K=128)
// ============================================================
__global__ __launch_bounds__(256) void syrk_kernel()
{
    __shared__ float As[16][64];
    __shared__ float Bs[16][64];
    const float* Z = g_z + (size_t)blockIdx.z * SEQ * F2;
    float* C = g_corr + (size_t)blockIdx.z * SEQ * SEQ;
    const int m0 = blockIdx.y * 64, n0 = blockIdx.x * 64;
    const int tid = threadIdx.x;
    const int ty = tid >> 4, tx = tid & 15;
    const int row = tid >> 2, kq = tid & 3;

    float acc[4][4] = {};

    for (int k0 = 0; k0 < F2; k0 += 16) {
        float4 va = *(const float4*)(Z + (size_t)(m0 + row) * F2 + k0 + kq * 4);
        As[kq*4+0][row] = va.x; As[kq*4+1][row] = va.y;
        As[kq*4+2][row] = va.z; As[kq*4+3][row] = va.w;
        float4 vb = *(const float4*)(Z + (size_t)(n0 + row) * F2 + k0 + kq * 4);
        Bs[kq*4+0][row] = vb.x; Bs[kq*4+1][row] = vb.y;
        Bs[kq*4+2][row] = vb.z; Bs[kq*4+3][row] = vb.w;
        __syncthreads();
        #pragma unroll
        for (int k = 0; k < 16; k++) {
            float4 a4 = *(const float4*)&As[k][ty*4];
            float4 b4 = *(const float4*)&Bs[k][tx*4];
            float av[4] = {a4.x, a4.y, a4.z, a4.w};
            float bv[4] = {b4.x, b4.y, b4.z, b4.w};
            #pragma unroll
            for (int r = 0; r < 4; r++)
                #pragma unroll
                for (int c = 0; c < 4; c++)
                    acc[r][c] += av[r] * bv[c];
        }
        __syncthreads();
    }

    #pragma unroll
    for (int r = 0; r < 4; r++) {
        int m = m0 + ty*4 + r;
        #pragma unroll
        for (int c = 0; c < 4; c++) {
            int n = n0 + tx*4 + c;
            C[(size_t)m * SEQ + n] = acc[r][c];
        }
    }
}

// ============================================================
// Fused: D = (1 - corr/sqrt(max(dn*di,1e-8)))/2  AND cumsum over n.
// One block per batch, thread = column i, sequential left-fold in n
// (matches jnp.cumsum order exactly).
// ============================================================
__global__ __launch_bounds__(256) void computeD_scan_kernel()
{
    const int b = blockIdx.x, i = threadIdx.x;
    const float* cb = g_corr + (size_t)b * SEQ * SEQ;
    float* Db = g_D   + (size_t)b * SEQ * SEQ;
    float* Tb = g_tmp + (size_t)b * SEQ * SEQ;
    __shared__ float sdiag[SEQ];
    sdiag[i] = cb[i * SEQ + i];
    __syncthreads();
    const float di = sdiag[i];
    float run = 0.0f;
    for (int n = 0; n < SEQ; n++) {
        float dn = sdiag[n];
        float denom = sqrtf(fmaxf(dn * di, 1e-8f));
        float d = (1.0f - cb[n*SEQ + i] / denom) * 0.5f;
        Db[n*SEQ + i] = d;
        run += d;
        Tb[n*SEQ + i] = run;
    }
}

// cumsum over i (axis=2), sequential left-fold
__global__ __launch_bounds__(256) void scan_cols_kernel()
{
    const int b = blockIdx.x, n = threadIdx.x;
    const float* Tb = g_tmp + (size_t)b * SEQ * SEQ;
    float* Pb = g_P + (size_t)b * SEQ * SEQ;
    float run = 0.0f;
    for (int i = 0; i < SEQ; i++) { run += Tb[n*SEQ + i]; Pb[n*SEQ + i] = run; }
}

// Ds[n][i] = 4-corner block formula; subdiag -> D.
// Also: init DP C-vector (column 255) and zero the barrier counters.
__global__ __launch_bounds__(256) void buildDs_kernel()
{
    const int b = blockIdx.y, n = blockIdx.x, i = threadIdx.x;
    const float* Pb = g_P + (size_t)b * SEQ * SEQ;
    const float* Db = g_D + (size_t)b * SEQ * SEQ;
    int lo = min(n, i), hi = max(n, i);
    float a  = Pb[hi*SEQ + hi];
    float bb = (lo == 0) ? 0.0f : Pb[(lo-1)*SEQ + hi];
    float cc = (lo == 0) ? 0.0f : Pb[hi*SEQ + (lo-1)];
    float dd = (lo == 0) ? 0.0f : Pb[(lo-1)*SEQ + (lo-1)];
    float v = ((a - bb) - cc) + dd;
    if (n - i == 1) v = Db[n*SEQ + i];
    g_Ds[(size_t)b*SEQ*SEQ + n*SEQ + i] = v;
    if (i == SEQ - 1) g_Cbuf[0][b][n] = v;                  // C_prev init
    if (n == 0 && b == 0 && i < BATCH*KMAX)
        ((int*)g_ctr)[i] = 0;                               // barrier counters
}

// ============================================================
// Phase C: 30-step DP spread across the chip.
// grid = (BATCH, PCB): 16 blocks x 16 warps per batch = 256 warps,
// one row per warp per step. Per-batch spin barrier between steps.
// Lane l permanently owns columns l+32j -> register accumulator.
// ============================================================
__global__ __launch_bounds__(PCT) void phaseC_kernel()
{
    __shared__ float s_acc[PCT/32][SEQ];   // 16KB, used only at the end
    const int b = blockIdx.x, blk = blockIdx.y;
    const int tid = threadIdx.x, w = tid >> 5, l = tid & 31;
    const int wb = blk * (PCT/32) + w;     // global row id within batch, 0..255
    const float* Ds = g_Ds + (size_t)b * SEQ * SEQ;
    const float* row = Ds + (size_t)wb * SEQ;

    float acc[8] = {};

    for (int kk = 1; kk < KMAX; kk++) {
        const int limit = SEQ - kk;
        const float* Cprev = g_Cbuf[(kk - 1) & 1][b];
        if (wb < limit) {
            float t[8];
            float mn = 3.0e38f;
            #pragma unroll
            for (int j = 0; j < 8; j++) {
                int i = l + 32*j;
                bool valid = (i >= wb) & (i < limit);
                // __ldcg: bypass (possibly stale) L1 for the cross-SM C vector
                float v = valid ? (row[i] + __ldcg(&Cprev[i + 1])) : 3.0e38f;
                t[j] = v;
                mn = fminf(mn, v);
            }
            #pragma unroll
            for (int off = 16; off > 0; off >>= 1)
                mn = fminf(mn, __shfl_xor_sync(0xffffffffu, mn, off));

            float e[8];
            float s = 0.0f;
            #pragma unroll
            for (int j = 0; j < 8; j++) {
                e[j] = __expf(mn - t[j]);   // invalid lanes: mn-3e38 -> exp = 0
                s += e[j];
            }
            #pragma unroll
            for (int off = 16; off > 0; off >>= 1)
                s += __shfl_xor_sync(0xffffffffu, s, off);

            float inv = __fdividef(1.0f, s);
            #pragma unroll
            for (int j = 0; j < 8; j++) acc[j] += e[j] * inv;

            if (l == 0) g_Cbuf[kk & 1][b][wb] = mn;   // Cmin == softmax shift
        }

        // ---- per-batch barrier across the PCB blocks ----
        __syncthreads();
        if (tid == 0) {
            __threadfence();                 // release Cnext writes
            atomicAdd(&g_ctr[b][kk], 1);
            volatile int* p = &g_ctr[b][kk];
            while (*p < PCB) { }
            __threadfence();                 // acquire (also flushes L1)
        }
        __syncthreads();
    }

    // block-level reduction of register accumulators
    #pragma unroll
    for (int j = 0; j < 8; j++) s_acc[w][l + 32*j] = acc[j];
    __syncthreads();
    if (tid < SEQ) {
        float sum = 0.0f;
        #pragma unroll
        for (int ww = 0; ww < PCT/32; ww++) sum += s_acc[ww][tid];
        g_part[b][blk][tid] = sum;
    }
}

// out[b][i] = (sum of partials + k0 term) / exact mask count
__global__ __launch_bounds__(256) void finalize_kernel(float* __restrict__ out)
{
    const int b = blockIdx.x, i = threadIdx.x;
    float num = (i == SEQ - 1) ? (float)SEQ : 0.0f;   // k=0 plane: col 255 = 1
    #pragma unroll
    for (int p = 0; p < PCB; p++) num += g_part[b][p][i];
    int m = min(KMAX - 1, SEQ - 1 - i);
    float cnt = (float)((i + 1) * m + ((i == SEQ - 1) ? SEQ : 0));
    out[b*SEQ + i] = num / cnt;
}

// ============================================================
extern "C" void kernel_launch(void* const* d_in, const int* in_sizes, int n_in,
                              void* d_out, int out_size)
{
    const float* x  = (const float*)d_in[0];
    const float* W0 = (const float*)d_in[1];
    const float* b0 = (const float*)d_in[2];
    const float* W1 = (const float*)d_in[3];
    const float* b1 = (const float*)d_in[4];
    float* out = (float*)d_out;

    static float* p_h = nullptr;
    static float* p_z = nullptr;
    if (!p_h) {
        cudaGetSymbolAddress((void**)&p_h, g_h);
        cudaGetSymbolAddress((void**)&p_z, g_z);
    }

    gemm_kernel<1><<<dim3(F1/64, (BATCH*SEQ)/64), 256>>>(x,   W0, b0, p_h, BATCH*SEQ, F1, F0);
    gemm_kernel<0><<<dim3(F2/64, (BATCH*SEQ)/64), 256>>>(p_h, W1, b1, p_z, BATCH*SEQ, F2, F1);
    syrk_kernel      <<<dim3(SEQ/64, SEQ/64, BATCH), 256>>>();
    computeD_scan_kernel<<<BATCH, SEQ>>>();
    scan_cols_kernel <<<BATCH, SEQ>>>();
    buildDs_kernel   <<<dim3(SEQ, BATCH), SEQ>>>();
    phaseC_kernel    <<<dim3(BATCH, PCB), PCT>>>();
    finalize_kernel  <<<BATCH, SEQ>>>(out);
}

// round 3
// speedup vs baseline: 2.7955x; 1.8430x over previous
#include <cuda_runtime.h>
#include <math.h>

#define BATCH 8
#define SEQ   256
#define F0    512
#define F1    256
#define F2    128
#define KMAX  30
#define PCB   16      // phaseC blocks per batch (8*16 = 128 blocks, one wave)
#define PCT   512     // threads per phaseC block (16 warps)
#define NSEG  8       // row-scan segments (32 rows each)

// ---- scratch (__device__ globals; no allocations allowed) ----
__device__ float g_h[BATCH*SEQ*F1];
__device__ float g_z[BATCH*SEQ*F2];
__device__ float g_corr[BATCH*SEQ*SEQ];
__device__ float g_tmp[BATCH*SEQ*SEQ];
__device__ float g_P[BATCH*SEQ*SEQ];       // 2-D inclusive prefix sums
__device__ float g_Ds[BATCH*SEQ*SEQ];
__device__ float g_diag[BATCH][SEQ];       // diag of corr
__device__ float g_seg[BATCH][NSEG][SEQ];  // per-segment row-scan totals
__device__ float g_segp[BATCH][NSEG][SEQ]; // exclusive prefix of seg totals
__device__ float g_Cbuf[2][BATCH][SEQ];    // DP C-vector, double buffered
__device__ int   g_ctr[BATCH][KMAX];       // per-step arrival counters
__device__ float g_part[BATCH][PCB][SEQ];  // per-block partial numerators

// ============================================================
// GEMM: C[M,N] = (A[M,K] @ B[K,N]) + bias, optional relu.
// ============================================================
template<int RELU>
__global__ __launch_bounds__(256) void gemm_kernel(
    const float* __restrict__ A, const float* __restrict__ B,
    const float* __restrict__ bias, float* __restrict__ C,
    int M, int N, int K)
{
    __shared__ float As[16][64];
    __shared__ float Bs[16][64];
    const int m0 = blockIdx.y * 64, n0 = blockIdx.x * 64;
    const int tid = threadIdx.x;
    const int ty = tid >> 4, tx = tid & 15;
    const int arow = tid >> 2, akq = tid & 3;
    const int bkr  = tid >> 4, bnq = tid & 15;

    float acc[4][4] = {};

    for (int k0 = 0; k0 < K; k0 += 16) {
        float4 va = *(const float4*)(A + (size_t)(m0 + arow) * K + k0 + akq * 4);
        As[akq*4+0][arow] = va.x; As[akq*4+1][arow] = va.y;
        As[akq*4+2][arow] = va.z; As[akq*4+3][arow] = va.w;
        float4 vb = *(const float4*)(B + (size_t)(k0 + bkr) * N + n0 + bnq * 4);
        *(float4*)&Bs[bkr][bnq*4] = vb;
        __syncthreads();
        #pragma unroll
        for (int k = 0; k < 16; k++) {
            float4 a4 = *(const float4*)&As[k][ty*4];
            float4 b4 = *(const float4*)&Bs[k][tx*4];
            float av[4] = {a4.x, a4.y, a4.z, a4.w};
            float bv[4] = {b4.x, b4.y, b4.z, b4.w};
            #pragma unroll
            for (int r = 0; r < 4; r++)
                #pragma unroll
                for (int c = 0; c < 4; c++)
                    acc[r][c] += av[r] * bv[c];
        }
        __syncthreads();
    }

    #pragma unroll
    for (int r = 0; r < 4; r++) {
        int m = m0 + ty*4 + r;
        #pragma unroll
        for (int c = 0; c < 4; c++) {
            int n = n0 + tx*4 + c;
            float v = acc[r][c] + bias[n];
            if (RELU) v = fmaxf(v, 0.0f);
            C[(size_t)m * N + n] = v;
        }
    }
}

// ============================================================
// corr[b] = z_b @ z_b^T; also captures the diagonal into g_diag.
// ============================================================
__global__ __launch_bounds__(256) void syrk_kernel()
{
    __shared__ float As[16][64];
    __shared__ float Bs[16][64];
    const int bz = blockIdx.z;
    const float* Z = g_z + (size_t)bz * SEQ * F2;
    float* C = g_corr + (size_t)bz * SEQ * SEQ;
    const int m0 = blockIdx.y * 64, n0 = blockIdx.x * 64;
    const int tid = threadIdx.x;
    const int ty = tid >> 4, tx = tid & 15;
    const int row = tid >> 2, kq = tid & 3;

    float acc[4][4] = {};

    for (int k0 = 0; k0 < F2; k0 += 16) {
        float4 va = *(const float4*)(Z + (size_t)(m0 + row) * F2 + k0 + kq * 4);
        As[kq*4+0][row] = va.x; As[kq*4+1][row] = va.y;
        As[kq*4+2][row] = va.z; As[kq*4+3][row] = va.w;
        float4 vb = *(const float4*)(Z + (size_t)(n0 + row) * F2 + k0 + kq * 4);
        Bs[kq*4+0][row] = vb.x; Bs[kq*4+1][row] = vb.y;
        Bs[kq*4+2][row] = vb.z; Bs[kq*4+3][row] = vb.w;
        __syncthreads();
        #pragma unroll
        for (int k = 0; k < 16; k++) {
            float4 a4 = *(const float4*)&As[k][ty*4];
            float4 b4 = *(const float4*)&Bs[k][tx*4];
            float av[4] = {a4.x, a4.y, a4.z, a4.w};
            float bv[4] = {b4.x, b4.y, b4.z, b4.w};
            #pragma unroll
            for (int r = 0; r < 4; r++)
                #pragma unroll
                for (int c = 0; c < 4; c++)
                    acc[r][c] += av[r] * bv[c];
        }
        __syncthreads();
    }

    #pragma unroll
    for (int r = 0; r < 4; r++) {
        int m = m0 + ty*4 + r;
        #pragma unroll
        for (int c = 0; c < 4; c++) {
            int n = n0 + tx*4 + c;
            C[(size_t)m * SEQ + n] = acc[r][c];
            if (m == n) g_diag[bz][m] = acc[r][c];
        }
    }
}

// ============================================================
// Fused D + segmented row-scan (axis n). Block = (segment, batch),
// 32 rows per segment, fully unrolled -> 32 loads in flight.
// ============================================================
__global__ __launch_bounds__(256) void computeD_seg_kernel()
{
    const int s = blockIdx.x, b = blockIdx.y, i = threadIdx.x;
    const float* cb = g_corr + (size_t)b * SEQ * SEQ;
    float* Tb = g_tmp + (size_t)b * SEQ * SEQ + (size_t)s * 32 * SEQ;
    __shared__ float sdn[32];
    if (i < 32) sdn[i] = g_diag[b][s*32 + i];
    const float di = g_diag[b][i];
    __syncthreads();
    float run = 0.0f;
    #pragma unroll
    for (int n = 0; n < 32; n++) {
        float denom = sqrtf(fmaxf(sdn[n] * di, 1e-8f));
        float d = (1.0f - cb[(size_t)(s*32 + n) * SEQ + i] / denom) * 0.5f;
        run += d;
        Tb[n*SEQ + i] = run;
    }
    g_seg[b][s][i] = run;
}

// exclusive prefix over segment totals (left-fold, per column)
__global__ __launch_bounds__(256) void scan_seg_kernel()
{
    const int b = blockIdx.x, i = threadIdx.x;
    float run = 0.0f;
    #pragma unroll
    for (int s = 0; s < NSEG; s++) {
        g_segp[b][s][i] = run;
        run += g_seg[b][s][i];
    }
}

// ============================================================
// Col-scan (axis i): one warp per row; lane owns 8 contiguous
// floats; local prefix + shfl_up warp scan; adds segment offset.
// ============================================================
__global__ __launch_bounds__(256) void colscan_kernel()
{
    const int b = blockIdx.y;
    const int tid = threadIdx.x, w = tid >> 5, l = tid & 31;
    const int n = blockIdx.x * 8 + w;
    const float* T = g_tmp + (size_t)b * SEQ * SEQ + (size_t)n * SEQ;
    const float* off = g_segp[b][n >> 5];
    float* P = g_P + (size_t)b * SEQ * SEQ + (size_t)n * SEQ;

    float4 a0 = *(const float4*)(T + l*8);
    float4 a1 = *(const float4*)(T + l*8 + 4);
    float4 o0 = *(const float4*)(off + l*8);
    float4 o1 = *(const float4*)(off + l*8 + 4);
    float v[8] = {a0.x+o0.x, a0.y+o0.y, a0.z+o0.z, a0.w+o0.w,
                  a1.x+o1.x, a1.y+o1.y, a1.z+o1.z, a1.w+o1.w};
    #pragma unroll
    for (int j = 1; j < 8; j++) v[j] += v[j-1];
    float tot = v[7];
    float inc = tot;
    #pragma unroll
    for (int d2 = 1; d2 < 32; d2 <<= 1) {
        float t2 = __shfl_up_sync(0xffffffffu, inc, d2);
        if (l >= d2) inc += t2;
    }
    float excl = inc - tot;
    #pragma unroll
    for (int j = 0; j < 8; j++) v[j] += excl;
    *(float4*)(P + l*8)     = make_float4(v[0], v[1], v[2], v[3]);
    *(float4*)(P + l*8 + 4) = make_float4(v[4], v[5], v[6], v[7]);
}

// ============================================================
// Ds[n][i] = 4-corner formula; subdiag recomputed from corr.
// Also inits the DP C-vector and zeroes the barrier counters.
// ============================================================
__global__ __launch_bounds__(256) void buildDs_kernel()
{
    const int b = blockIdx.y, n = blockIdx.x, i = threadIdx.x;
    const float* Pb = g_P + (size_t)b * SEQ * SEQ;
    int lo = min(n, i), hi = max(n, i);
    float a  = Pb[hi*SEQ + hi];
    float bb = (lo == 0) ? 0.0f : Pb[(lo-1)*SEQ + hi];
    float cc = (lo == 0) ? 0.0f : Pb[hi*SEQ + (lo-1)];
    float dd = (lo == 0) ? 0.0f : Pb[(lo-1)*SEQ + (lo-1)];
    float v = ((a - bb) - cc) + dd;
    if (n - i == 1) {
        float denom = sqrtf(fmaxf(g_diag[b][n] * g_diag[b][i], 1e-8f));
        v = (1.0f - g_corr[(size_t)b*SEQ*SEQ + n*SEQ + i] / denom) * 0.5f;
    }
    g_Ds[(size_t)b*SEQ*SEQ + n*SEQ + i] = v;
    if (i == SEQ - 1) g_Cbuf[0][b][n] = v;
    if (n == 0 && b == 0 && i < BATCH*KMAX)
        ((int*)g_ctr)[i] = 0;
}

// ============================================================
// Phase C: 30-step DP across the chip (128 blocks, one wave).
// ============================================================
__global__ __launch_bounds__(PCT) void phaseC_kernel()
{
    __shared__ float s_acc[PCT/32][SEQ];
    const int b = blockIdx.x, blk = blockIdx.y;
    const int tid = threadIdx.x, w = tid >> 5, l = tid & 31;
    const int wb = blk * (PCT/32) + w;
    const float* Ds = g_Ds + (size_t)b * SEQ * SEQ;
    const float* row = Ds + (size_t)wb * SEQ;

    float acc[8] = {};

    for (int kk = 1; kk < KMAX; kk++) {
        const int limit = SEQ - kk;
        const float* Cprev = g_Cbuf[(kk - 1) & 1][b];
        if (wb < limit) {
            float t[8];
            float mn = 3.0e38f;
            #pragma unroll
            for (int j = 0; j < 8; j++) {
                int i = l + 32*j;
                bool valid = (i >= wb) & (i < limit);
                float v = valid ? (row[i] + __ldcg(&Cprev[i + 1])) : 3.0e38f;
                t[j] = v;
                mn = fminf(mn, v);
            }
            #pragma unroll
            for (int off = 16; off > 0; off >>= 1)
                mn = fminf(mn, __shfl_xor_sync(0xffffffffu, mn, off));

            float e[8];
            float s = 0.0f;
            #pragma unroll
            for (int j = 0; j < 8; j++) {
                e[j] = __expf(mn - t[j]);
                s += e[j];
            }
            #pragma unroll
            for (int off = 16; off > 0; off >>= 1)
                s += __shfl_xor_sync(0xffffffffu, s, off);

            float inv = __fdividef(1.0f, s);
            #pragma unroll
            for (int j = 0; j < 8; j++) acc[j] += e[j] * inv;

            if (l == 0) g_Cbuf[kk & 1][b][wb] = mn;
        }

        __syncthreads();
        if (tid == 0) {
            __threadfence();
            atomicAdd(&g_ctr[b][kk], 1);
            volatile int* p = &g_ctr[b][kk];
            while (*p < PCB) { }
            __threadfence();
        }
        __syncthreads();
    }

    #pragma unroll
    for (int j = 0; j < 8; j++) s_acc[w][l + 32*j] = acc[j];
    __syncthreads();
    if (tid < SEQ) {
        float sum = 0.0f;
        #pragma unroll
        for (int ww = 0; ww < PCT/32; ww++) sum += s_acc[ww][tid];
        g_part[b][blk][tid] = sum;
    }
}

// out[b][i] = (sum of partials + k0 term) / exact mask count
__global__ __launch_bounds__(256) void finalize_kernel(float* __restrict__ out)
{
    const int b = blockIdx.x, i = threadIdx.x;
    float num = (i == SEQ - 1) ? (float)SEQ : 0.0f;
    #pragma unroll
    for (int p = 0; p < PCB; p++) num += g_part[b][p][i];
    int m = min(KMAX - 1, SEQ - 1 - i);
    float cnt = (float)((i + 1) * m + ((i == SEQ - 1) ? SEQ : 0));
    out[b*SEQ + i] = num / cnt;
}

// ============================================================
extern "C" void kernel_launch(void* const* d_in, const int* in_sizes, int n_in,
                              void* d_out, int out_size)
{
    const float* x  = (const float*)d_in[0];
    const float* W0 = (const float*)d_in[1];
    const float* b0 = (const float*)d_in[2];
    const float* W1 = (const float*)d_in[3];
    const float* b1 = (const float*)d_in[4];
    float* out = (float*)d_out;

    static float* p_h = nullptr;
    static float* p_z = nullptr;
    if (!p_h) {
        cudaGetSymbolAddress((void**)&p_h, g_h);
        cudaGetSymbolAddress((void**)&p_z, g_z);
    }

    gemm_kernel<1><<<dim3(F1/64, (BATCH*SEQ)/64), 256>>>(x,   W0, b0, p_h, BATCH*SEQ, F1, F0);
    gemm_kernel<0><<<dim3(F2/64, (BATCH*SEQ)/64), 256>>>(p_h, W1, b1, p_z, BATCH*SEQ, F2, F1);
    syrk_kernel       <<<dim3(SEQ/64, SEQ/64, BATCH), 256>>>();
    computeD_seg_kernel<<<dim3(NSEG, BATCH), SEQ>>>();
    scan_seg_kernel   <<<BATCH, SEQ>>>();
    colscan_kernel    <<<dim3(SEQ/8, BATCH), 256>>>();
    buildDs_kernel    <<<dim3(SEQ, BATCH), SEQ>>>();
    phaseC_kernel     <<<dim3(BATCH, PCB), PCT>>>();
    finalize_kernel   <<<BATCH, SEQ>>>(out);
}